// round 2
// baseline (speedup 1.0000x reference)
#include <cuda_runtime.h>
#include <math.h>

// Problem constants (shapes fixed by the dataset)
#define N_ROWS   65536
#define D_LAT    64
#define KC       64
#define D_DATA   512
#define N_ITERS  10

#define GRID_ITER 512   // blocks for iter kernel (2 tiles each, 1024 tiles)
#define GRID_DEC  2048  // blocks for decoder-loss kernel

#define LDE 68   // smem stride for enc tile (pad, float4-aligned)
#define LDR 68   // smem stride for r tile

// -------- scratch (static device globals: allocation-free) --------
__device__ float g_C[KC * D_LAT];
__device__ float g_c2[KC];
__device__ float g_x2[N_ROWS];
__device__ float g_partC[GRID_ITER * KC * D_LAT];   // 8 MB
__device__ float g_partR[GRID_ITER * KC];
__device__ float g_partLoss[GRID_ITER];
__device__ float g_decPart[GRID_DEC];

// -------- x2[n] = sum_d enc[n][d]^2 (once) --------
__global__ void x2_kernel(const float* __restrict__ enc) {
    int warp = threadIdx.x >> 5, lane = threadIdx.x & 31;
    int row = blockIdx.x * 8 + warp;
    const float2* e = reinterpret_cast<const float2*>(enc + (size_t)row * D_LAT);
    float2 v = e[lane];
    float s = v.x * v.x + v.y * v.y;
    #pragma unroll
    for (int off = 16; off; off >>= 1) s += __shfl_xor_sync(0xffffffffu, s, off);
    if (lane == 0) g_x2[row] = s;
}

// -------- C init = enc[:K]; c2 init --------
__global__ void initC_kernel(const float* __restrict__ enc) {
    int k = blockIdx.x, d = threadIdx.x;
    float c = enc[k * D_LAT + d];
    g_C[k * D_LAT + d] = c;
    __shared__ float sh[64];
    sh[d] = c * c;
    __syncthreads();
    for (int off = 32; off; off >>= 1) {
        if (d < off) sh[d] += sh[d + off];
        __syncthreads();
    }
    if (d == 0) g_c2[k] = sh[0];
}

// -------- one soft-kmeans iteration (fused d2 -> softmax -> partial C) --------
__global__ void __launch_bounds__(128)
iter_kernel(const float* __restrict__ enc, int doLoss, int doUpdate) {
    extern __shared__ float smem[];
    float* sEnc = smem;                 // [64][LDE]  enc tile, row-major
    float* sCt  = sEnc + 64 * LDE;      // [64][64]   C transposed: [d][k]
    float* sR   = sCt + 64 * 64;        // [64][LDR]  d2 then r
    float* sX2  = sR + 64 * LDR;        // [64]
    float* sC2  = sX2 + 64;             // [64]
    float* sRed = sC2 + 64;             // [128]

    int t = threadIdx.x;
    int tx = t & 15, ty = t >> 4;       // thread tile: rows ty*8+i, cols tx*4+j

    // load C (transposed) + c2 once per block
    for (int idx = t; idx < KC * D_LAT; idx += 128) {
        int k = idx >> 6, d = idx & 63;
        sCt[d * 64 + k] = g_C[idx];
    }
    if (t < 64) sC2[t] = g_c2[t];

    float cacc[8][4];                   // partial C accumulators: k=ty*8+i, d=tx*4+j
    #pragma unroll
    for (int i = 0; i < 8; i++)
        #pragma unroll
        for (int j = 0; j < 4; j++) cacc[i][j] = 0.f;
    float rcolAcc = 0.f;                // column sum of r for col t>>1 (half rows)
    float lossAcc = 0.f;

    for (int tile = blockIdx.x; tile < N_ROWS / 64; tile += GRID_ITER) {
        __syncthreads();   // protect smem reuse (and C-load visibility on 1st pass)
        int rowBase = tile * 64;
        const float4* eg = reinterpret_cast<const float4*>(enc + (size_t)rowBase * D_LAT);
        for (int idx = t; idx < 64 * 16; idx += 128) {
            int r = idx >> 4, c4 = idx & 15;
            *reinterpret_cast<float4*>(&sEnc[r * LDE + c4 * 4]) = eg[r * 16 + c4];
        }
        if (t < 64) sX2[t] = g_x2[rowBase + t];
        __syncthreads();

        // ---- gemm1: dot[i][j] = enc_row . C_k ----
        float acc[8][4];
        #pragma unroll
        for (int i = 0; i < 8; i++)
            #pragma unroll
            for (int j = 0; j < 4; j++) acc[i][j] = 0.f;

        #pragma unroll
        for (int d0 = 0; d0 < 64; d0 += 4) {
            float4 b0 = *reinterpret_cast<const float4*>(&sCt[(d0 + 0) * 64 + tx * 4]);
            float4 b1 = *reinterpret_cast<const float4*>(&sCt[(d0 + 1) * 64 + tx * 4]);
            float4 b2 = *reinterpret_cast<const float4*>(&sCt[(d0 + 2) * 64 + tx * 4]);
            float4 b3 = *reinterpret_cast<const float4*>(&sCt[(d0 + 3) * 64 + tx * 4]);
            #pragma unroll
            for (int i = 0; i < 8; i++) {
                float4 a = *reinterpret_cast<const float4*>(&sEnc[(ty * 8 + i) * LDE + d0]);
                acc[i][0] += a.x * b0.x + a.y * b1.x + a.z * b2.x + a.w * b3.x;
                acc[i][1] += a.x * b0.y + a.y * b1.y + a.z * b2.y + a.w * b3.y;
                acc[i][2] += a.x * b0.z + a.y * b1.z + a.z * b2.z + a.w * b3.z;
                acc[i][3] += a.x * b0.w + a.y * b1.w + a.z * b2.w + a.w * b3.w;
            }
        }

        // ---- d2 = max(x2 + c2 - 2 dot, 0) -> sR ----
        #pragma unroll
        for (int i = 0; i < 8; i++) {
            float x2v = sX2[ty * 8 + i];
            float4 dv;
            dv.x = fmaxf(x2v + sC2[tx * 4 + 0] - 2.f * acc[i][0], 0.f);
            dv.y = fmaxf(x2v + sC2[tx * 4 + 1] - 2.f * acc[i][1], 0.f);
            dv.z = fmaxf(x2v + sC2[tx * 4 + 2] - 2.f * acc[i][2], 0.f);
            dv.w = fmaxf(x2v + sC2[tx * 4 + 3] - 2.f * acc[i][3], 0.f);
            *reinterpret_cast<float4*>(&sR[(ty * 8 + i) * LDR + tx * 4]) = dv;
        }
        __syncthreads();

        // ---- row softmax of -d2 (2 threads per row), fuse loss on last iter ----
        {
            int row = t >> 1;
            float* rp = &sR[row * LDR + (t & 1) * 32];
            float mn = 3.4e38f;
            #pragma unroll 8
            for (int c = 0; c < 32; c++) mn = fminf(mn, rp[c]);
            mn = fminf(mn, __shfl_xor_sync(0xffffffffu, mn, 1));
            float s = 0.f, sl = 0.f;
            #pragma unroll 8
            for (int c = 0; c < 32; c++) {
                float d2 = rp[c];
                float e = __expf(mn - d2);
                s += e;
                sl += e * d2;
                rp[c] = e;
            }
            s  += __shfl_xor_sync(0xffffffffu, s, 1);
            sl += __shfl_xor_sync(0xffffffffu, sl, 1);
            float inv = 1.f / s;
            #pragma unroll 8
            for (int c = 0; c < 32; c++) rp[c] *= inv;
            if (doLoss && (t & 1) == 0) lossAcc += sl * inv;   // sum_k r*d2 for this row
        }
        __syncthreads();

        if (doUpdate) {
            // column sums of r (denominator)
            {
                int col = t >> 1, r0 = (t & 1) * 32;
                float s = 0.f;
                #pragma unroll 8
                for (int r = 0; r < 32; r++) s += sR[(r0 + r) * LDR + col];
                rcolAcc += s;
            }
            // ---- gemm2: Cpart[k][d] += r[row][k] * enc[row][d] ----
            #pragma unroll 4
            for (int row = 0; row < 64; row++) {
                float4 ev = *reinterpret_cast<const float4*>(&sEnc[row * LDE + tx * 4]);
                const float* rp = &sR[row * LDR + ty * 8];
                #pragma unroll
                for (int i = 0; i < 8; i++) {
                    float ri = rp[i];
                    cacc[i][0] += ri * ev.x;
                    cacc[i][1] += ri * ev.y;
                    cacc[i][2] += ri * ev.z;
                    cacc[i][3] += ri * ev.w;
                }
            }
        }
    }

    if (doUpdate) {
        float* dst = &g_partC[(size_t)blockIdx.x * (KC * D_LAT)];
        #pragma unroll
        for (int i = 0; i < 8; i++) {
            float4 v = make_float4(cacc[i][0], cacc[i][1], cacc[i][2], cacc[i][3]);
            *reinterpret_cast<float4*>(&dst[(ty * 8 + i) * 64 + tx * 4]) = v;
        }
        float tot = rcolAcc + __shfl_xor_sync(0xffffffffu, rcolAcc, 1);
        if ((t & 1) == 0) g_partR[blockIdx.x * KC + (t >> 1)] = tot;
    }
    if (doLoss) {
        sRed[t] = lossAcc;
        __syncthreads();
        for (int off = 64; off; off >>= 1) {
            if (t < off) sRed[t] += sRed[t + off];
            __syncthreads();
        }
        if (t == 0) g_partLoss[blockIdx.x] = sRed[0];
    }
}

// -------- reduce block partials -> C_new, c2 --------
__global__ void reduce_kernel() {
    int k = blockIdx.x, d = threadIdx.x;
    float s = 0.f;
    #pragma unroll 8
    for (int b = 0; b < GRID_ITER; b++) s += g_partC[(size_t)b * (KC * D_LAT) + k * D_LAT + d];
    float rs = 0.f;
    #pragma unroll 8
    for (int b = 0; b < GRID_ITER; b++) rs += g_partR[b * KC + k];
    float c = s / (rs + 1e-8f);
    g_C[k * D_LAT + d] = c;
    __shared__ float sh[64];
    sh[d] = c * c;
    __syncthreads();
    for (int off = 32; off; off >>= 1) {
        if (d < off) sh[d] += sh[d + off];
        __syncthreads();
    }
    if (d == 0) g_c2[k] = sh[0];
}

// -------- decoder loss partials --------
__global__ void dec_kernel(const float* __restrict__ X, const float* __restrict__ dec) {
    const float4* x4 = reinterpret_cast<const float4*>(X);
    const float4* d4 = reinterpret_cast<const float4*>(dec);
    int idx = blockIdx.x * blockDim.x + threadIdx.x;
    const int total4 = (N_ROWS * D_DATA) / 4;   // 8388608
    const int stride = GRID_DEC * 256;
    float s = 0.f;
    for (int i = idx; i < total4; i += stride) {
        float4 a = x4[i], b = d4[i];
        float dx = a.x - b.x, dy = a.y - b.y, dz = a.z - b.z, dw = a.w - b.w;
        s += dx * dx + dy * dy + dz * dz + dw * dw;
    }
    __shared__ float sh[256];
    sh[threadIdx.x] = s;
    __syncthreads();
    for (int off = 128; off; off >>= 1) {
        if (threadIdx.x < off) sh[threadIdx.x] += sh[threadIdx.x + off];
        __syncthreads();
    }
    if (threadIdx.x == 0) g_decPart[blockIdx.x] = sh[0];
}

// -------- final combine --------
__global__ void final_kernel(float* out) {
    __shared__ double sh[256];
    int t = threadIdx.x;
    double s = 0.0;
    for (int i = t; i < GRID_DEC; i += 256) s += (double)g_decPart[i];
    sh[t] = s;
    __syncthreads();
    for (int off = 128; off; off >>= 1) {
        if (t < off) sh[t] += sh[t + off];
        __syncthreads();
    }
    double decSum = sh[0];
    __syncthreads();
    sh[t] = (double)g_partLoss[t] + (double)g_partLoss[t + 256];
    __syncthreads();
    for (int off = 128; off; off >>= 1) {
        if (t < off) sh[t] += sh[t + off];
        __syncthreads();
    }
    if (t == 0) {
        double decLoss = decSum / ((double)N_ROWS * (double)D_DATA);
        double clLoss  = sh[0] / (double)N_ROWS;
        out[0] = (float)(decLoss + 0.001 * clLoss);
    }
}

extern "C" void kernel_launch(void* const* d_in, const int* in_sizes, int n_in,
                              void* d_out, int out_size) {
    const float* X   = (const float*)d_in[0];
    const float* enc = (const float*)d_in[1];
    const float* dec = (const float*)d_in[2];
    float* out = (float*)d_out;

    const int smemIter = (64 * LDE + 64 * 64 + 64 * LDR + 64 + 64 + 128) * (int)sizeof(float); // 52224
    cudaFuncSetAttribute(iter_kernel, cudaFuncAttributeMaxDynamicSharedMemorySize, smemIter);

    dec_kernel<<<GRID_DEC, 256>>>(X, dec);
    x2_kernel<<<N_ROWS / 8, 256>>>(enc);
    initC_kernel<<<KC, 64>>>(enc);
    for (int it = 0; it < N_ITERS; it++) {
        int last = (it == N_ITERS - 1);
        iter_kernel<<<GRID_ITER, 128, smemIter>>>(enc, last, !last);
        if (!last) reduce_kernel<<<KC, 64>>>();
    }
    final_kernel<<<1, 256>>>(out);
}

// round 4
// speedup vs baseline: 2.5086x; 2.5086x over previous
#include <cuda_runtime.h>
#include <cstdint>

// ---------------- problem constants ----------------
#define N_ROWS  65536
#define D_LAT   64
#define KC      64
#define D_DATA  512
#define N_ITERS 10

#define TILE     128
#define NTILES   (N_ROWS / TILE)       // 512
#define GRID_IT  128
#define TPB      (NTILES / GRID_IT)    // 4
#define GRID_DEC 2048

// smem float offsets
#define SF_C2   0
#define SF_RED  64
#define SF_ENC  320                    // [128][76]
#define SF_CT   (SF_ENC + 128*76)      // [64][72]  C^T: [d][k]
#define SF_R    (SF_CT + 64*72)        // [128][72] r:  [n][k]
#define SF_TOT  (SF_R + 128*72)        // 23872 floats = 95488 B

// ---------------- scratch globals ----------------
__device__ float g_C[KC * D_LAT];
__device__ float g_c2[KC];
__device__ float g_x2[N_ROWS];
__device__ float g_partC[GRID_IT * KC * D_LAT];
__device__ float g_partR[GRID_IT * KC];
__device__ float g_partLoss[GRID_IT];
__device__ float g_decPart[GRID_DEC];

// ---------------- mma.sync tf32 (m16n8k8) ----------------
__device__ __forceinline__ void mma_tf32(float* c, uint32_t a0, uint32_t a1,
                                         uint32_t a2, uint32_t a3,
                                         uint32_t b0, uint32_t b1) {
    asm volatile(
        "mma.sync.aligned.m16n8k8.row.col.f32.tf32.tf32.f32 "
        "{%0,%1,%2,%3}, {%4,%5,%6,%7}, {%8,%9}, {%0,%1,%2,%3};"
        : "+f"(c[0]), "+f"(c[1]), "+f"(c[2]), "+f"(c[3])
        : "r"(a0), "r"(a1), "r"(a2), "r"(a3), "r"(b0), "r"(b1));
}
__device__ __forceinline__ uint32_t fb(float x) { return __float_as_uint(x); }

// ---------------- small kernels ----------------
__global__ void x2_kernel(const float* __restrict__ enc) {
    int warp = threadIdx.x >> 5, lane = threadIdx.x & 31;
    int row = blockIdx.x * 8 + warp;
    const float2* e = reinterpret_cast<const float2*>(enc + (size_t)row * D_LAT);
    float2 v = e[lane];
    float s = v.x * v.x + v.y * v.y;
    #pragma unroll
    for (int off = 16; off; off >>= 1) s += __shfl_xor_sync(0xffffffffu, s, off);
    if (lane == 0) g_x2[row] = s;
}

__global__ void initC_kernel(const float* __restrict__ enc) {
    int k = blockIdx.x, d = threadIdx.x;
    float c = enc[k * D_LAT + d];
    g_C[k * D_LAT + d] = c;
    __shared__ float sh[64];
    sh[d] = c * c;
    __syncthreads();
    for (int off = 32; off; off >>= 1) { if (d < off) sh[d] += sh[d + off]; __syncthreads(); }
    if (d == 0) g_c2[k] = sh[0];
}

// 16 blocks x 256 threads: block covers 4 k-rows; thread -> one (k,d) output
__global__ void reduce_kernel() {
    int t = threadIdx.x;
    int k = blockIdx.x * 4 + (t >> 6), d = t & 63;
    float s = 0.f;
    #pragma unroll 8
    for (int b = 0; b < GRID_IT; b++) s += g_partC[(size_t)b * 4096 + k * 64 + d];
    __shared__ float srs[4];
    if (t < 128) {
        int j = t >> 5, ln = t & 31;
        float rs = 0.f;
        #pragma unroll
        for (int b = ln; b < GRID_IT; b += 32) rs += g_partR[b * 64 + blockIdx.x * 4 + j];
        #pragma unroll
        for (int off = 16; off; off >>= 1) rs += __shfl_xor_sync(0xffffffffu, rs, off);
        if (ln == 0) srs[j] = rs;
    }
    __syncthreads();
    float c = s / (srs[t >> 6] + 1e-8f);
    g_C[k * 64 + d] = c;
    __shared__ float sh[256];
    sh[t] = c * c;
    __syncthreads();
    for (int off = 32; off; off >>= 1) { if (d < off) sh[t] += sh[t + off]; __syncthreads(); }
    if (d == 0) g_c2[k] = sh[t];
}

__global__ void dec_kernel(const float* __restrict__ X, const float* __restrict__ dec) {
    const float4* x4 = reinterpret_cast<const float4*>(X);
    const float4* d4 = reinterpret_cast<const float4*>(dec);
    int idx = blockIdx.x * blockDim.x + threadIdx.x;
    const int total4 = (N_ROWS * D_DATA) / 4;
    const int stride = GRID_DEC * 256;
    float s = 0.f;
    for (int i = idx; i < total4; i += stride) {
        float4 a = x4[i], b = d4[i];
        float dx = a.x - b.x, dy = a.y - b.y, dz = a.z - b.z, dw = a.w - b.w;
        s += dx * dx + dy * dy + dz * dz + dw * dw;
    }
    __shared__ float sh[256];
    sh[threadIdx.x] = s;
    __syncthreads();
    for (int off = 128; off; off >>= 1) { if (threadIdx.x < off) sh[threadIdx.x] += sh[threadIdx.x + off]; __syncthreads(); }
    if (threadIdx.x == 0) g_decPart[blockIdx.x] = sh[0];
}

__global__ void final_kernel(float* out) {
    __shared__ double sh[256];
    int t = threadIdx.x;
    double s = 0.0;
    for (int i = t; i < GRID_DEC; i += 256) s += (double)g_decPart[i];
    sh[t] = s;
    __syncthreads();
    for (int off = 128; off; off >>= 1) { if (t < off) sh[t] += sh[t + off]; __syncthreads(); }
    double decSum = sh[0];
    __syncthreads();
    sh[t] = (t < GRID_IT) ? (double)g_partLoss[t] : 0.0;
    __syncthreads();
    for (int off = 128; off; off >>= 1) { if (t < off) sh[t] += sh[t + off]; __syncthreads(); }
    if (t == 0) {
        double decLoss = decSum / ((double)N_ROWS * (double)D_DATA);
        double clLoss  = sh[0] / (double)N_ROWS;
        out[0] = (float)(decLoss + 0.001 * clLoss);
    }
}

// ---------------- main per-iteration kernel (mma.sync tf32) ----------------
__global__ void __launch_bounds__(256, 1)
iter_kernel(const float* __restrict__ enc, int doLoss, int doUpdate) {
    extern __shared__ float sm[];
    float* sC2  = sm + SF_C2;
    float* sEnc = sm + SF_ENC;
    float* sCt  = sm + SF_CT;
    float* sR   = sm + SF_R;

    int t = threadIdx.x, w = t >> 5, lane = t & 31;
    int qr = lane >> 2, qc = lane & 3;   // quad row / quad col

    // ---- one-time setup: C^T, c2, ones column ----
    for (int idx = t; idx < 4096; idx += 256) {
        int k = idx >> 6, d = idx & 63;
        sCt[d * 72 + k] = g_C[idx];
    }
    if (t < 64) sC2[t] = g_c2[t];
    if (t < 128) {
        sEnc[t * 76 + 64] = 1.0f;
        #pragma unroll
        for (int c = 65; c < 72; c++) sEnc[t * 76 + c] = 0.0f;
    }

    // per-thread c2 values for the epilogue (cols nt*8 + qc*2 + {0,1})
    float c2v[8][2];
    // (valid after first __syncthreads below; preload after sync)

    // gemm2 accumulators persist across tiles
    float acc2[5][4];
    #pragma unroll
    for (int i = 0; i < 5; i++)
        #pragma unroll
        for (int j = 0; j < 4; j++) acc2[i][j] = 0.f;

    int mb2  = (w & 3) * 16;          // gemm2 m-tile base (k-cluster rows)
    int ntlo = (w < 4) ? 0 : 4;
    int nN   = (w < 4) ? 4 : 5;

    float lossAcc = 0.f;
    bool c2loaded = false;

    for (int tt = 0; tt < TPB; tt++) {
        int n0 = (blockIdx.x * TPB + tt) * TILE;
        __syncthreads();   // prev gemm2 done reading sEnc/sR (and setup on tt=0)

        // ---- load enc tile [128][64] -> sEnc stride 76 ----
        const float4* eg = reinterpret_cast<const float4*>(enc + (size_t)n0 * D_LAT);
        #pragma unroll
        for (int i = 0; i < 8; i++) {
            int idx = i * 256 + t;
            int r = idx >> 4, c4 = idx & 15;
            *reinterpret_cast<float4*>(&sEnc[r * 76 + c4 * 4]) = eg[idx];
        }
        float x2a = g_x2[n0 + w * 16 + qr];
        float x2b = g_x2[n0 + w * 16 + qr + 8];
        __syncthreads();

        if (!c2loaded) {
            c2loaded = true;
            #pragma unroll
            for (int nt = 0; nt < 8; nt++) {
                c2v[nt][0] = sC2[nt * 8 + qc * 2];
                c2v[nt][1] = sC2[nt * 8 + qc * 2 + 1];
            }
        }

        // ---- gemm1: D1[128 rows][64 k] = enc @ C^T ; warp w -> rows w*16..+15 ----
        float acc1[8][4];
        #pragma unroll
        for (int nt = 0; nt < 8; nt++)
            #pragma unroll
            for (int j = 0; j < 4; j++) acc1[nt][j] = 0.f;

        {
            const float* eRow = sEnc + (w * 16 + qr) * 76;
            #pragma unroll
            for (int ks = 0; ks < 8; ks++) {
                uint32_t a0 = fb(eRow[ks * 8 + qc]);
                uint32_t a1 = fb(eRow[8 * 76 + ks * 8 + qc]);
                uint32_t a2 = fb(eRow[ks * 8 + qc + 4]);
                uint32_t a3 = fb(eRow[8 * 76 + ks * 8 + qc + 4]);
                const float* ctk = sCt + (ks * 8 + qc) * 72;
                #pragma unroll
                for (int nt = 0; nt < 8; nt++) {
                    uint32_t b0 = fb(ctk[nt * 8 + qr]);
                    uint32_t b1 = fb(ctk[4 * 72 + nt * 8 + qr]);
                    mma_tf32(acc1[nt], a0, a1, a2, a3, b0, b1);
                }
            }
        }

        // ---- epilogue: d2, row softmax (rows r0=w*16+qr and r0+8) ----
        float mn0 = 3.4e38f, mn1 = 3.4e38f;
        #pragma unroll
        for (int nt = 0; nt < 8; nt++) {
            acc1[nt][0] = fmaxf(x2a + c2v[nt][0] - 2.f * acc1[nt][0], 0.f);
            acc1[nt][1] = fmaxf(x2a + c2v[nt][1] - 2.f * acc1[nt][1], 0.f);
            acc1[nt][2] = fmaxf(x2b + c2v[nt][0] - 2.f * acc1[nt][2], 0.f);
            acc1[nt][3] = fmaxf(x2b + c2v[nt][1] - 2.f * acc1[nt][3], 0.f);
            mn0 = fminf(mn0, fminf(acc1[nt][0], acc1[nt][1]));
            mn1 = fminf(mn1, fminf(acc1[nt][2], acc1[nt][3]));
        }
        mn0 = fminf(mn0, __shfl_xor_sync(0xffffffffu, mn0, 1));
        mn0 = fminf(mn0, __shfl_xor_sync(0xffffffffu, mn0, 2));
        mn1 = fminf(mn1, __shfl_xor_sync(0xffffffffu, mn1, 1));
        mn1 = fminf(mn1, __shfl_xor_sync(0xffffffffu, mn1, 2));

        float s0 = 0.f, s1 = 0.f, sl0 = 0.f, sl1 = 0.f;
        #pragma unroll
        for (int nt = 0; nt < 8; nt++) {
            float d2, e;
            d2 = acc1[nt][0]; e = __expf(mn0 - d2); s0 += e; sl0 += e * d2; acc1[nt][0] = e;
            d2 = acc1[nt][1]; e = __expf(mn0 - d2); s0 += e; sl0 += e * d2; acc1[nt][1] = e;
            d2 = acc1[nt][2]; e = __expf(mn1 - d2); s1 += e; sl1 += e * d2; acc1[nt][2] = e;
            d2 = acc1[nt][3]; e = __expf(mn1 - d2); s1 += e; sl1 += e * d2; acc1[nt][3] = e;
        }
        s0 += __shfl_xor_sync(0xffffffffu, s0, 1);  s0 += __shfl_xor_sync(0xffffffffu, s0, 2);
        s1 += __shfl_xor_sync(0xffffffffu, s1, 1);  s1 += __shfl_xor_sync(0xffffffffu, s1, 2);
        sl0 += __shfl_xor_sync(0xffffffffu, sl0, 1); sl0 += __shfl_xor_sync(0xffffffffu, sl0, 2);
        sl1 += __shfl_xor_sync(0xffffffffu, sl1, 1); sl1 += __shfl_xor_sync(0xffffffffu, sl1, 2);
        float inv0 = 1.f / s0, inv1 = 1.f / s1;
        if (doLoss) lossAcc += sl0 * inv0 * 0.25f + sl1 * inv1 * 0.25f;  // each quad-lane counts row/4

        if (doUpdate) {
            // ---- store r [n][k] stride 72 ----
            float* r0p = &sR[(w * 16 + qr) * 72];
            float* r1p = r0p + 8 * 72;
            #pragma unroll
            for (int nt = 0; nt < 8; nt++) {
                int col = nt * 8 + qc * 2;
                r0p[col]     = acc1[nt][0] * inv0;
                r0p[col + 1] = acc1[nt][1] * inv0;
                r1p[col]     = acc1[nt][2] * inv1;
                r1p[col + 1] = acc1[nt][3] * inv1;
            }
            __syncthreads();

            // ---- gemm2: D2[64 k][72] += r^T @ [enc | 1] ----
            #pragma unroll
            for (int ks = 0; ks < 16; ks++) {
                const float* rA = sR + (ks * 8 + qc) * 72 + mb2 + qr;
                const float* rB = sR + (ks * 8 + qc + 4) * 72 + mb2 + qr;
                uint32_t a0 = fb(rA[0]);
                uint32_t a1 = fb(rA[8]);
                uint32_t a2 = fb(rB[0]);
                uint32_t a3 = fb(rB[8]);
                const float* e0 = sEnc + (ks * 8 + qc) * 76 + qr;
                const float* e1 = sEnc + (ks * 8 + qc + 4) * 76 + qr;
                #pragma unroll
                for (int i = 0; i < 5; i++) {
                    if (i < nN) {
                        int nt = ntlo + i;
                        uint32_t b0 = fb(e0[nt * 8]);
                        uint32_t b1 = fb(e1[nt * 8]);
                        mma_tf32(acc2[i], a0, a1, a2, a3, b0, b1);
                    }
                }
            }
        }
    }

    // ---- write per-block partials ----
    if (doUpdate) {
        int k0 = mb2 + qr, k1 = k0 + 8;
        size_t base = (size_t)blockIdx.x * 4096;
        #pragma unroll
        for (int i = 0; i < 5; i++) {
            if (i < nN) {
                int nt = ntlo + i;
                if (nt < 8) {
                    int d = nt * 8 + qc * 2;
                    *reinterpret_cast<float2*>(&g_partC[base + k0 * 64 + d]) = make_float2(acc2[i][0], acc2[i][1]);
                    *reinterpret_cast<float2*>(&g_partC[base + k1 * 64 + d]) = make_float2(acc2[i][2], acc2[i][3]);
                } else if (qc == 0) {
                    g_partR[blockIdx.x * 64 + k0] = acc2[i][0];
                    g_partR[blockIdx.x * 64 + k1] = acc2[i][2];
                }
            }
        }
    }
    if (doLoss) {
        float* red = sm + SF_RED;
        red[t] = lossAcc;
        __syncthreads();
        for (int off = 128; off; off >>= 1) { if (t < off) red[t] += red[t + off]; __syncthreads(); }
        if (t == 0) g_partLoss[blockIdx.x] = red[0];
    }
}

// ---------------- launch ----------------
extern "C" void kernel_launch(void* const* d_in, const int* in_sizes, int n_in,
                              void* d_out, int out_size) {
    const float* X   = (const float*)d_in[0];
    const float* enc = (const float*)d_in[1];
    const float* dec = (const float*)d_in[2];
    float* out = (float*)d_out;

    const int smemIter = SF_TOT * (int)sizeof(float);   // 95488 B
    cudaFuncSetAttribute(iter_kernel, cudaFuncAttributeMaxDynamicSharedMemorySize, smemIter);

    dec_kernel<<<GRID_DEC, 256>>>(X, dec);
    x2_kernel<<<N_ROWS / 8, 256>>>(enc);
    initC_kernel<<<KC, 64>>>(enc);
    for (int it = 0; it < N_ITERS; it++) {
        int last = (it == N_ITERS - 1);
        iter_kernel<<<GRID_IT, 256, smemIter>>>(enc, last, !last);
        if (!last) reduce_kernel<<<16, 256>>>();
    }
    final_kernel<<<1, 256>>>(out);
}